// round 14
// baseline (speedup 1.0000x reference)
#include <cuda_runtime.h>
#include <cuda_bf16.h>

#define N_NODES 100000
#define N_EDGES 1200000
#define DIM 64

// Scratch (cudaMalloc is forbidden). Static zero-init seeds the
// "agg/deg are zero at kernel_launch entry" invariant; phase2 restores it.
__device__ float g_agg[(size_t)N_NODES * DIM];
__device__ float g_deg[N_NODES];
__device__ float g_hx[(size_t)N_NODES * DIM];   // x-half GEMM result

// ---------------------------------------------------------------------------
// f32x2 packed helpers (sm_103; ptxas never auto-fuses these from C++)
// ---------------------------------------------------------------------------
__device__ __forceinline__ unsigned long long ffma2(unsigned long long a,
                                                    unsigned long long b,
                                                    unsigned long long c) {
    unsigned long long d;
    asm("fma.rn.f32x2 %0, %1, %2, %3;" : "=l"(d) : "l"(a), "l"(b), "l"(c));
    return d;
}
__device__ __forceinline__ float2 unpack2(unsigned long long a) {
    float2 r;
    asm("mov.b64 {%0, %1}, %2;" : "=f"(r.x), "=f"(r.y) : "l"(a));
    return r;
}

// ---------------------------------------------------------------------------
// Phase 1: fused edge scatter + x-half GEMM (independent of scatter).
// Block interleave: every 49th block is a GEMM block (1563 of 76563);
// GEMM blocks live ~4x longer -> ~8% steady-state residency, hidden
// inside the L2-bound scatter window.
// ---------------------------------------------------------------------------
#define GEMM_BLOCKS 1563       // ceil(100000/64)
#define EDGE_BLOCKS 75000      // 1.2M edges / 16 per block
#define B_STRIDE    49
#define TOTAL_B     (GEMM_BLOCKS + EDGE_BLOCKS)
#define WPAD2       68         // 64-float row padded; 16B aligned
#define TM 4

#define P1_SMEM ((64 * WPAD2 + 64 * 64) * 4)

__global__ __launch_bounds__(256)
void phase1_kernel(const float* __restrict__ x,
                   const float* __restrict__ W,       // [64][128]
                   const void* __restrict__ ei_raw) {
    const int g   = blockIdx.x;
    const int gq  = g / B_STRIDE;
    const int tid = threadIdx.x;

    if (g % B_STRIDE == 0 && gq < GEMM_BLOCKS) {
        // ---------------- x-half GEMM block: hx = x . Wx^T ----------------
        extern __shared__ float sm[];
        float* Wsh  = sm;              // [64][WPAD2]
        float* insh = sm + 64 * WPAD2; // [64][64]
        const int base = gq * 64;

        for (int i = tid; i < 64 * 16; i += 256) {
            int c = i >> 4, kq = i & 15;
            *reinterpret_cast<float4*>(&Wsh[c * WPAD2 + kq * 4]) =
                reinterpret_cast<const float4*>(W)[c * 32 + kq];   // k in [0,64)
        }
        for (int i = tid; i < 64 * 16; i += 256) {
            int n = i >> 4, kq = i & 15;
            int gn = base + n;
            float4 v = make_float4(0.f, 0.f, 0.f, 0.f);
            if (gn < N_NODES)
                v = reinterpret_cast<const float4*>(x + (size_t)gn * DIM)[kq];
            *reinterpret_cast<float4*>(&insh[n * 64 + kq * 4]) = v;
        }
        __syncthreads();

        const int cg = tid & 15;
        const int ng = (tid >> 4) & 1;
        const int warp = tid >> 5;
        const int nodeBase = warp * 8 + ng * TM;

        unsigned long long acc[4][TM];
        #pragma unroll
        for (int t = 0; t < 4; t++)
            #pragma unroll
            for (int m = 0; m < TM; m++) acc[t][m] = 0ull;

        const float* ip  = insh + nodeBase * 64;
        const float* wp0 = Wsh + (cg +  0) * WPAD2;
        const float* wp1 = Wsh + (cg + 16) * WPAD2;
        const float* wp2 = Wsh + (cg + 32) * WPAD2;
        const float* wp3 = Wsh + (cg + 48) * WPAD2;

        #pragma unroll 4
        for (int kq = 0; kq < 16; kq++) {
            ulonglong2 w0 = *reinterpret_cast<const ulonglong2*>(wp0 + kq * 4);
            ulonglong2 w1 = *reinterpret_cast<const ulonglong2*>(wp1 + kq * 4);
            ulonglong2 w2 = *reinterpret_cast<const ulonglong2*>(wp2 + kq * 4);
            ulonglong2 w3 = *reinterpret_cast<const ulonglong2*>(wp3 + kq * 4);
            #pragma unroll
            for (int m = 0; m < TM; m++) {
                ulonglong2 iv = *reinterpret_cast<const ulonglong2*>(ip + m * 64 + kq * 4);
                acc[0][m] = ffma2(iv.x, w0.x, acc[0][m]);
                acc[0][m] = ffma2(iv.y, w0.y, acc[0][m]);
                acc[1][m] = ffma2(iv.x, w1.x, acc[1][m]);
                acc[1][m] = ffma2(iv.y, w1.y, acc[1][m]);
                acc[2][m] = ffma2(iv.x, w2.x, acc[2][m]);
                acc[2][m] = ffma2(iv.y, w2.y, acc[2][m]);
                acc[3][m] = ffma2(iv.x, w3.x, acc[3][m]);
                acc[3][m] = ffma2(iv.y, w3.y, acc[3][m]);
            }
        }
        #pragma unroll
        for (int m = 0; m < TM; m++) {
            int gn = (gq * 64) + nodeBase + m;
            if (gn < N_NODES) {
                float* op = g_hx + (size_t)gn * DIM + cg;
                #pragma unroll
                for (int t = 0; t < 4; t++) {
                    float2 a = unpack2(acc[t][m]);
                    op[16 * t] = a.x + a.y;
                }
            }
        }
    } else {
        // ---------------- edge scatter block: 16 edges, 16 thr/edge --------
        const int eb = g - (gq + 1);
        __shared__ int sIdx64;
        if (tid < 32) {
            int w = ((const int*)ei_raw)[2 * tid + 1];
            unsigned b = __ballot_sync(0xFFFFFFFFu, w != 0);
            if (tid == 0) sIdx64 = (b == 0u);   // all-zero odd words -> int64
        }
        __syncthreads();

        int e = eb * 16 + (tid >> 4);
        int c = tid & 15;
        long long i, j;
        if (sIdx64) {
            const long long* ei = (const long long*)ei_raw;
            i = ei[e];
            j = ei[N_EDGES + e];
        } else {
            const int* ei = (const int*)ei_raw;
            i = ei[e];
            j = ei[N_EDGES + e];
        }
        const float4* xr = reinterpret_cast<const float4*>(x + j * DIM);
        float4 v = xr[c];
        float* dst = g_agg + i * DIM + c * 4;
        asm volatile("red.global.add.v4.f32 [%0], {%1, %2, %3, %4};"
                     :: "l"(dst), "f"(v.x), "f"(v.y), "f"(v.z), "f"(v.w)
                     : "memory");
        if (c == 0) atomicAdd(g_deg + i, 1.0f);
    }
}

// ---------------------------------------------------------------------------
// Phase 2: agg-half GEMM + hx + bias + ReLU + LayerNorm.
// Re-zeros g_agg / g_deg after consuming them (same-thread read-then-zero;
// no clamped duplicate accesses) so phase1 finds zeros on the next replay.
// ---------------------------------------------------------------------------
#define P2_SMEM ((64 * WPAD2 + 64 * 64 + 64 * 64 + 64) * 4)

__global__ __launch_bounds__(256)
void phase2_kernel(const float* __restrict__ W,      // [64][128]
                   const float* __restrict__ bias,
                   const float* __restrict__ gamma,
                   const float* __restrict__ beta,
                   float* __restrict__ out) {
    extern __shared__ float sm[];
    float* Wsh   = sm;                    // [64][WPAD2]  (agg half of W)
    float* aggsh = sm + 64 * WPAD2;       // [64][64]
    float* hxsh  = aggsh + 64 * 64;       // [64][64]
    float* shinv = hxsh + 64 * 64;        // [64]

    const int tid  = threadIdx.x;
    const int base = blockIdx.x * 64;

    for (int i = tid; i < 64 * 16; i += 256) {
        int c = i >> 4, kq = i & 15;
        *reinterpret_cast<float4*>(&Wsh[c * WPAD2 + kq * 4]) =
            reinterpret_cast<const float4*>(W)[c * 32 + 16 + kq];  // k in [64,128)
    }
    if (tid < 64) {
        int gn = base + tid;
        if (gn < N_NODES) {
            shinv[tid] = 1.0f / fmaxf(g_deg[gn], 1.0f);
            g_deg[gn] = 0.f;                         // re-zero for next replay
        } else {
            shinv[tid] = 0.f;
        }
    }
    __syncthreads();

    for (int i = tid; i < 64 * 16; i += 256) {
        int n = i >> 4, kq = i & 15;
        int gn = base + n;
        float4 a = make_float4(0.f, 0.f, 0.f, 0.f);
        float4 h = a;
        if (gn < N_NODES) {
            float4* ap = reinterpret_cast<float4*>(g_agg + (size_t)gn * DIM) + kq;
            a = *ap;
            *ap = make_float4(0.f, 0.f, 0.f, 0.f);   // re-zero for next replay
            float inv = shinv[n];
            a.x *= inv; a.y *= inv; a.z *= inv; a.w *= inv;
            h = reinterpret_cast<const float4*>(g_hx + (size_t)gn * DIM)[kq];
        }
        *reinterpret_cast<float4*>(&aggsh[n * 64 + kq * 4]) = a;
        *reinterpret_cast<float4*>(&hxsh[n * 64 + kq * 4])  = h;
    }
    __syncthreads();

    const int cg = tid & 15;
    const int ng = (tid >> 4) & 1;
    const int warp = tid >> 5;
    const int nodeBase = warp * 8 + ng * TM;

    unsigned long long acc[4][TM];
    #pragma unroll
    for (int t = 0; t < 4; t++)
        #pragma unroll
        for (int m = 0; m < TM; m++) acc[t][m] = 0ull;

    const float* ip  = aggsh + nodeBase * 64;
    const float* wp0 = Wsh + (cg +  0) * WPAD2;
    const float* wp1 = Wsh + (cg + 16) * WPAD2;
    const float* wp2 = Wsh + (cg + 32) * WPAD2;
    const float* wp3 = Wsh + (cg + 48) * WPAD2;

    #pragma unroll 4
    for (int kq = 0; kq < 16; kq++) {
        ulonglong2 w0 = *reinterpret_cast<const ulonglong2*>(wp0 + kq * 4);
        ulonglong2 w1 = *reinterpret_cast<const ulonglong2*>(wp1 + kq * 4);
        ulonglong2 w2 = *reinterpret_cast<const ulonglong2*>(wp2 + kq * 4);
        ulonglong2 w3 = *reinterpret_cast<const ulonglong2*>(wp3 + kq * 4);
        #pragma unroll
        for (int m = 0; m < TM; m++) {
            ulonglong2 iv = *reinterpret_cast<const ulonglong2*>(ip + m * 64 + kq * 4);
            acc[0][m] = ffma2(iv.x, w0.x, acc[0][m]);
            acc[0][m] = ffma2(iv.y, w0.y, acc[0][m]);
            acc[1][m] = ffma2(iv.x, w1.x, acc[1][m]);
            acc[1][m] = ffma2(iv.y, w1.y, acc[1][m]);
            acc[2][m] = ffma2(iv.x, w2.x, acc[2][m]);
            acc[2][m] = ffma2(iv.y, w2.y, acc[2][m]);
            acc[3][m] = ffma2(iv.x, w3.x, acc[3][m]);
            acc[3][m] = ffma2(iv.y, w3.y, acc[3][m]);
        }
    }

    // Epilogue: + hx + bias -> ReLU -> LN over 16-lane col group -> store.
    float bi[4];
    #pragma unroll
    for (int t = 0; t < 4; t++) bi[t] = bias[cg + 16 * t];

    float h[4][TM], sv[TM], qv[TM];
    #pragma unroll
    for (int m = 0; m < TM; m++) {
        float s = 0.f, q = 0.f;
        const float* hxr = hxsh + (nodeBase + m) * 64;
        #pragma unroll
        for (int t = 0; t < 4; t++) {
            float2 a = unpack2(acc[t][m]);
            float v = fmaxf(a.x + a.y + hxr[cg + 16 * t] + bi[t], 0.f);
            h[t][m] = v;
            s += v;
            q += v * v;
        }
        sv[m] = s; qv[m] = q;
    }
    #pragma unroll
    for (int off = 8; off > 0; off >>= 1) {
        #pragma unroll
        for (int m = 0; m < TM; m++) {
            sv[m] += __shfl_xor_sync(0xFFFFFFFFu, sv[m], off);
            qv[m] += __shfl_xor_sync(0xFFFFFFFFu, qv[m], off);
        }
    }

    float ga[4], be[4];
    #pragma unroll
    for (int t = 0; t < 4; t++) {
        ga[t] = gamma[cg + 16 * t];
        be[t] = beta[cg + 16 * t];
    }
    #pragma unroll
    for (int m = 0; m < TM; m++) {
        int gn = base + nodeBase + m;
        if (gn < N_NODES) {
            float mu   = sv[m] * (1.0f / DIM);
            float var  = qv[m] * (1.0f / DIM) - mu * mu;
            float rstd = rsqrtf(var + 1e-5f);
            float* op = out + (size_t)gn * DIM + cg;
            #pragma unroll
            for (int t = 0; t < 4; t++)
                op[16 * t] = (h[t][m] - mu) * rstd * ga[t] + be[t];
        }
    }
}

// ---------------------------------------------------------------------------
extern "C" void kernel_launch(void* const* d_in, const int* in_sizes, int n_in,
                              void* d_out, int out_size) {
    const float* x     = (const float*)d_in[0];   // [100000, 64]
    const float* W     = (const float*)d_in[1];   // [64, 128]
    const float* bias  = (const float*)d_in[2];   // [64]
    const float* gamma = (const float*)d_in[3];   // [64]
    const float* beta  = (const float*)d_in[4];   // [64]
    const void*  ei    = d_in[5];                 // [2, 1200000] int32 or int64
    float* out         = (float*)d_out;

    // Host-side attribute set (not a stream op; capture-safe, idempotent).
    cudaFuncSetAttribute(phase1_kernel,
                         cudaFuncAttributeMaxDynamicSharedMemorySize, P1_SMEM);
    cudaFuncSetAttribute(phase2_kernel,
                         cudaFuncAttributeMaxDynamicSharedMemorySize, P2_SMEM);

    // Phase 1: edge scatter + x-half GEMM, co-scheduled.
    phase1_kernel<<<TOTAL_B, 256, P1_SMEM>>>(x, W, ei);

    // Phase 2: agg-half GEMM + combine + LN (+ scratch re-zero).
    phase2_kernel<<<GEMM_BLOCKS, 256, P2_SMEM>>>(W, bias, gamma, beta, out);
}

// round 15
// speedup vs baseline: 1.7087x; 1.7087x over previous
#include <cuda_runtime.h>
#include <cuda_bf16.h>

#define N_NODES 100000
#define N_EDGES 1200000
#define DIM 64

// Scratch (cudaMalloc is forbidden). Static zero-init seeds the
// "agg/deg are zero at kernel_launch entry" invariant; node_kernel
// restores it every execution (read-then-zero), so graph replays see zeros.
__device__ float g_agg[(size_t)N_NODES * DIM];
__device__ float g_deg[N_NODES];
__device__ int   g_idx64;   // 1 if edge_index is int64, 0 if int32

// ---------------------------------------------------------------------------
// f32x2 packed helpers (sm_103; ptxas never auto-fuses these from C++)
// ---------------------------------------------------------------------------
__device__ __forceinline__ unsigned long long ffma2(unsigned long long a,
                                                    unsigned long long b,
                                                    unsigned long long c) {
    unsigned long long d;
    asm("fma.rn.f32x2 %0, %1, %2, %3;" : "=l"(d) : "l"(a), "l"(b), "l"(c));
    return d;
}
__device__ __forceinline__ float2 unpack2(unsigned long long a) {
    float2 r;
    asm("mov.b64 {%0, %1}, %2;" : "=f"(r.x), "=f"(r.y) : "l"(a));
    return r;
}

// ---------------------------------------------------------------------------
// Kernel 0: detect edge_index dtype. int64 indices < 2^31 -> all odd 32-bit
// words zero; impossible for 32 random int32 node indices.
// ---------------------------------------------------------------------------
__global__ void detect_kernel(const int* __restrict__ ei32) {
    int w = ei32[2 * threadIdx.x + 1];
    unsigned b = __ballot_sync(0xFFFFFFFFu, w != 0);
    if (threadIdx.x == 0) g_idx64 = (b == 0u);
}

// ---------------------------------------------------------------------------
// Kernel 1: edge scatter. 16 threads/edge, vector reduction atomics.
// At the LTS cap (~614 MB L2 traffic); unchanged from R12.
// ---------------------------------------------------------------------------
__global__ void edge_kernel(const float* __restrict__ x,
                            const void* __restrict__ ei_raw) {
    long long t = (long long)blockIdx.x * blockDim.x + threadIdx.x;
    int e = (int)(t >> 4);
    int c = (int)(t & 15);
    if (e >= N_EDGES) return;

    long long i, j;
    if (g_idx64) {
        const long long* ei = (const long long*)ei_raw;
        i = ei[e];
        j = ei[N_EDGES + e];
    } else {
        const int* ei = (const int*)ei_raw;
        i = ei[e];
        j = ei[N_EDGES + e];
    }

    const float4* xr = reinterpret_cast<const float4*>(x + j * DIM);
    float4 v = xr[c];
    float* dst = g_agg + i * DIM + c * 4;
    asm volatile("red.global.add.v4.f32 [%0], {%1, %2, %3, %4};"
                 :: "l"(dst), "f"(v.x), "f"(v.y), "f"(v.z), "f"(v.w)
                 : "memory");
    if (c == 0) {
        atomicAdd(g_deg + i, 1.0f);
    }
}

// ---------------------------------------------------------------------------
// Kernel 2: register-blocked GEMM + ReLU + LayerNorm (+ scratch re-zero).
// CTA: 256 threads, 64 nodes (3 CTAs/SM). Lane role: cg = tid&15 -> cols
// {cg, cg+16, cg+32, cg+48}; ng = (tid>>4)&1 -> node half (TM=4 nodes).
// Each g_agg float4 / g_deg word is read-then-zeroed by exactly ONE thread
// (guarded, no clamping) so the next replay finds zeros.
// ---------------------------------------------------------------------------
#define TM 4
#define NODES_PER_CTA 64
#define WPAD 132   // 528 B row stride: 16B-aligned

__global__ __launch_bounds__(256, 3)
void node_kernel(const float* __restrict__ x,
                 const float* __restrict__ W,      // [64][128]
                 const float* __restrict__ bias,   // [64]
                 const float* __restrict__ gamma,  // [64]
                 const float* __restrict__ beta,   // [64]
                 float* __restrict__ out) {
    extern __shared__ float sm[];
    float* Wsh   = sm;                           // [64][WPAD]
    float* insh  = sm + 64 * WPAD;               // [64][128]
    float* shinv = insh + NODES_PER_CTA * 128;   // [64]

    const int tid  = threadIdx.x;
    const int base = blockIdx.x * NODES_PER_CTA;

    // Stage W (coalesced global read, row-padded shared write)
    for (int i = tid; i < 64 * 32; i += 256) {
        int c = i >> 5, kq = i & 31;
        *reinterpret_cast<float4*>(&Wsh[c * WPAD + kq * 4]) =
            reinterpret_cast<const float4*>(W)[i];
    }
    // Stage inverse degrees; re-zero g_deg (unique thread per node)
    if (tid < NODES_PER_CTA) {
        int gn = base + tid;
        if (gn < N_NODES) {
            shinv[tid] = 1.0f / fmaxf(g_deg[gn], 1.0f);
            g_deg[gn] = 0.f;
        } else {
            shinv[tid] = 0.f;
        }
    }
    __syncthreads();

    // Stage concat inputs: insh[n][0:64]=x[n], insh[n][64:128]=agg[n]*inv.
    // g_agg is read-then-zeroed (unique thread per float4, guarded).
    for (int i = tid; i < NODES_PER_CTA * 32; i += 256) {
        int n = i >> 5, kq = i & 31;
        int gn = base + n;
        float4 v = make_float4(0.f, 0.f, 0.f, 0.f);
        if (gn < N_NODES) {
            if (kq < 16) {
                v = reinterpret_cast<const float4*>(x + (size_t)gn * DIM)[kq];
            } else {
                float4* ap = reinterpret_cast<float4*>(g_agg + (size_t)gn * DIM)
                             + (kq - 16);
                v = *ap;
                *ap = make_float4(0.f, 0.f, 0.f, 0.f);   // restore invariant
                float inv = shinv[n];
                v.x *= inv; v.y *= inv; v.z *= inv; v.w *= inv;
            }
        }
        *reinterpret_cast<float4*>(&insh[n * 128 + kq * 4]) = v;
    }
    __syncthreads();

    const int cg   = tid & 15;          // column group: cols cg + 16*t
    const int ng   = (tid >> 4) & 1;    // node half within warp
    const int warp = tid >> 5;
    const int nodeBase = warp * 8 + ng * TM;   // within CTA

    unsigned long long acc[4][TM];
    #pragma unroll
    for (int t = 0; t < 4; t++)
        #pragma unroll
        for (int m = 0; m < TM; m++) acc[t][m] = 0ull;

    const float* ip  = insh + nodeBase * 128;
    const float* wp0 = Wsh + (cg +  0) * WPAD;
    const float* wp1 = Wsh + (cg + 16) * WPAD;
    const float* wp2 = Wsh + (cg + 32) * WPAD;
    const float* wp3 = Wsh + (cg + 48) * WPAD;

    #pragma unroll 4
    for (int kq = 0; kq < 32; kq++) {
        ulonglong2 w0 = *reinterpret_cast<const ulonglong2*>(wp0 + kq * 4);
        ulonglong2 w1 = *reinterpret_cast<const ulonglong2*>(wp1 + kq * 4);
        ulonglong2 w2 = *reinterpret_cast<const ulonglong2*>(wp2 + kq * 4);
        ulonglong2 w3 = *reinterpret_cast<const ulonglong2*>(wp3 + kq * 4);
        #pragma unroll
        for (int m = 0; m < TM; m++) {
            ulonglong2 iv = *reinterpret_cast<const ulonglong2*>(ip + m * 128 + kq * 4);
            acc[0][m] = ffma2(iv.x, w0.x, acc[0][m]);
            acc[0][m] = ffma2(iv.y, w0.y, acc[0][m]);
            acc[1][m] = ffma2(iv.x, w1.x, acc[1][m]);
            acc[1][m] = ffma2(iv.y, w1.y, acc[1][m]);
            acc[2][m] = ffma2(iv.x, w2.x, acc[2][m]);
            acc[2][m] = ffma2(iv.y, w2.y, acc[2][m]);
            acc[3][m] = ffma2(iv.x, w3.x, acc[3][m]);
            acc[3][m] = ffma2(iv.y, w3.y, acc[3][m]);
        }
    }

    // Epilogue: halves + bias -> ReLU; LayerNorm over the 16-lane col group
    // (each 16-lane group holds all 64 cols of its TM nodes).
    float bi[4];
    #pragma unroll
    for (int t = 0; t < 4; t++) bi[t] = bias[cg + 16 * t];

    float h[4][TM], sv[TM], qv[TM];
    #pragma unroll
    for (int m = 0; m < TM; m++) {
        float s = 0.f, q = 0.f;
        #pragma unroll
        for (int t = 0; t < 4; t++) {
            float2 a = unpack2(acc[t][m]);
            float v = fmaxf(a.x + a.y + bi[t], 0.f);
            h[t][m] = v;
            s += v;
            q += v * v;
        }
        sv[m] = s; qv[m] = q;
    }
    #pragma unroll
    for (int off = 8; off > 0; off >>= 1) {       // xor<16: stays within group
        #pragma unroll
        for (int m = 0; m < TM; m++) {
            sv[m] += __shfl_xor_sync(0xFFFFFFFFu, sv[m], off);
            qv[m] += __shfl_xor_sync(0xFFFFFFFFu, qv[m], off);
        }
    }

    float ga[4], be[4];
    #pragma unroll
    for (int t = 0; t < 4; t++) {
        ga[t] = gamma[cg + 16 * t];
        be[t] = beta[cg + 16 * t];
    }
    #pragma unroll
    for (int m = 0; m < TM; m++) {
        int gn = base + nodeBase + m;
        if (gn < N_NODES) {
            float mu   = sv[m] * (1.0f / DIM);
            float var  = qv[m] * (1.0f / DIM) - mu * mu;
            float rstd = rsqrtf(var + 1e-5f);
            float* op = out + (size_t)gn * DIM + cg;
            #pragma unroll
            for (int t = 0; t < 4; t++)
                op[16 * t] = (h[t][m] - mu) * rstd * ga[t] + be[t];
        }
    }
}

// ---------------------------------------------------------------------------
extern "C" void kernel_launch(void* const* d_in, const int* in_sizes, int n_in,
                              void* d_out, int out_size) {
    const float* x     = (const float*)d_in[0];   // [100000, 64]
    const float* W     = (const float*)d_in[1];   // [64, 128]
    const float* bias  = (const float*)d_in[2];   // [64]
    const float* gamma = (const float*)d_in[3];   // [64]
    const float* beta  = (const float*)d_in[4];   // [64]
    const void*  ei    = d_in[5];                 // [2, 1200000] int32 or int64
    float* out         = (float*)d_out;

    // 0) dtype detect (tiny)
    detect_kernel<<<1, 32>>>((const int*)ei);

    // 1) edge scatter: 16 threads per edge
    {
        long long threads = (long long)N_EDGES * 16;
        int blocks = (int)((threads + 255) / 256);
        edge_kernel<<<blocks, 256>>>(x, ei);
    }

    // 2) node phase: 4-col register-blocked GEMM + LN + scratch re-zero
    {
        int smem = (64 * WPAD + NODES_PER_CTA * 128 + NODES_PER_CTA) * sizeof(float);
        cudaFuncSetAttribute(node_kernel,
                             cudaFuncAttributeMaxDynamicSharedMemorySize, smem);
        int blocks = (N_NODES + NODES_PER_CTA - 1) / NODES_PER_CTA;  // 1563
        node_kernel<<<blocks, 256, smem>>>(x, W, bias, gamma, beta, out);
    }
}